// round 1
// baseline (speedup 1.0000x reference)
#include <cuda_runtime.h>
#include <cuda_bf16.h>

// Fused kernel: per-batch mask reduction + row gather + blend.
// Inputs (metadata order):
//   d_in[0] hiddens  f32 [S,B,H]
//   d_in[1] cells    f32 [S,B,H]
//   d_in[2] init_hidden f32 [H]
//   d_in[3] init_cell   f32 [H]
//   d_in[4] hidden_masks i32 [S,B]
//   d_in[5] op           i32 [B]
// Output: f32 [2,B,H]  (hidden_ret then cell_ret)

__global__ __launch_bounds__(256)
void lstm_state_gather_kernel(
    const float* __restrict__ hiddens,
    const float* __restrict__ cells,
    const float* __restrict__ init_hidden,
    const float* __restrict__ init_cell,
    const int*   __restrict__ masks,
    const int*   __restrict__ op,
    float* __restrict__ out,
    int S, int B, int H)
{
    const int b   = blockIdx.x;
    const int tid = threadIdx.x;

    // ---- Phase 1: pos[b] = sum_s masks[s*B + b] ----
    int local = 0;
    for (int s = tid; s < S; s += blockDim.x)
        local += masks[(size_t)s * B + b];

    // warp reduce
    #pragma unroll
    for (int off = 16; off > 0; off >>= 1)
        local += __shfl_down_sync(0xffffffffu, local, off);

    __shared__ int warp_sums[8];
    __shared__ int s_pos;
    const int wid = tid >> 5;
    const int lid = tid & 31;
    if (lid == 0) warp_sums[wid] = local;
    __syncthreads();
    if (wid == 0) {
        int v = (lid < (blockDim.x >> 5)) ? warp_sums[lid] : 0;
        #pragma unroll
        for (int off = 4; off > 0; off >>= 1)
            v += __shfl_down_sync(0xffffffffu, v, off);
        if (lid == 0) s_pos = v;
    }
    __syncthreads();

    const int pos  = s_pos;                    // in [0, S]
    const int prev = (pos == 0) ? S : pos - 1; // mod(pos-1, S+1)

    const float a  = fabsf((float)op[b]);
    const float na = 1.0f - a;

    // Row pointer for stack index p: p==0 -> init row, else data row (p-1, b)
    const size_t rowstride = (size_t)B * H;
    const float* cur_h_row  = (pos  == 0) ? init_hidden : hiddens + (size_t)(pos  - 1) * rowstride + (size_t)b * H;
    const float* prev_h_row = (prev == 0) ? init_hidden : hiddens + (size_t)(prev - 1) * rowstride + (size_t)b * H;
    const float* cur_c_row  = (pos  == 0) ? init_cell   : cells   + (size_t)(pos  - 1) * rowstride + (size_t)b * H;
    const float* prev_c_row = (prev == 0) ? init_cell   : cells   + (size_t)(prev - 1) * rowstride + (size_t)b * H;

    float* out_h = out + (size_t)b * H;
    float* out_c = out + (size_t)B * H + (size_t)b * H;

    // ---- Phase 2: gather + blend, vectorized by float4 when possible ----
    if ((H & 3) == 0) {
        const int H4 = H >> 2;
        const float4* ch = (const float4*)cur_h_row;
        const float4* ph = (const float4*)prev_h_row;
        const float4* cc = (const float4*)cur_c_row;
        const float4* pc = (const float4*)prev_c_row;
        float4* oh = (float4*)out_h;
        float4* oc = (float4*)out_c;
        for (int i = tid; i < H4; i += blockDim.x) {
            float4 vch = ch[i], vph = ph[i];
            float4 vcc = cc[i], vpc = pc[i];
            float4 rh, rc;
            rh.x = vph.x * a + vch.x * na;
            rh.y = vph.y * a + vch.y * na;
            rh.z = vph.z * a + vch.z * na;
            rh.w = vph.w * a + vch.w * na;
            rc.x = vpc.x * a + vcc.x * na;
            rc.y = vpc.y * a + vcc.y * na;
            rc.z = vpc.z * a + vcc.z * na;
            rc.w = vpc.w * a + vcc.w * na;
            oh[i] = rh;
            oc[i] = rc;
        }
    } else {
        for (int i = tid; i < H; i += blockDim.x) {
            out_h[i] = prev_h_row[i] * a + cur_h_row[i] * na;
            out_c[i] = prev_c_row[i] * a + cur_c_row[i] * na;
        }
    }
}

extern "C" void kernel_launch(void* const* d_in, const int* in_sizes, int n_in,
                              void* d_out, int out_size)
{
    const float* hiddens     = (const float*)d_in[0];
    const float* cells       = (const float*)d_in[1];
    const float* init_hidden = (const float*)d_in[2];
    const float* init_cell   = (const float*)d_in[3];
    const int*   masks       = (const int*)d_in[4];
    const int*   op          = (const int*)d_in[5];
    float*       out         = (float*)d_out;

    const int H = in_sizes[2];          // init_hidden length
    const int B = in_sizes[5];          // op length
    const int S = in_sizes[4] / B;      // masks is [S,B]

    lstm_state_gather_kernel<<<B, 256>>>(hiddens, cells, init_hidden, init_cell,
                                         masks, op, out, S, B, H);
}